// round 10
// baseline (speedup 1.0000x reference)
#include <cuda_runtime.h>
#include <cuda_bf16.h>
#include <math.h>

#define S_WORDS 2048
#define LMAX    16
#define CE      256
#define WE      512
#define HDIM    1024
#define GC      (4*CE)     // 1024 gate rows, char LSTM
#define GW      (4*HDIM)   // 4096 gate rows, word LSTM
#define KC      (2*CE)     // 512  (x | h) for char LSTM
#define KW      (WE+CE)    // 768  (we | char_feat)
#define NBLK_WL 128        // persistent blocks for word LSTM (<= 148 SMs)
#define CWPB    16         // words per block, char LSTM / word gemm
#define XHS     18         // padded smem row stride (floats): 8B-aligned, low conflict

typedef unsigned long long ull;

// ---------------- device scratch (no allocations allowed) ----------------
__device__ float g_WcT[KC*GC];        // [k=512][g=1024] transposed char weights
__device__ float g_WihwT[KW*GW];      // [k=768][g=4096] transposed word input weights
__device__ float g_lasth[S_WORDS*CE]; // char-LSTM output feature per word
__device__ float g_GXw[S_WORDS*GW];   // precomputed x-part of word-LSTM gates (+bias)
// tagged h broadcast: high 32 bits = step tag, low 32 bits = h bits. Double-buffered.
__device__ ull g_hpair[2*HDIM];

__device__ __forceinline__ float sigf(float x) { return 1.f / (1.f + __expf(-x)); }
__device__ __forceinline__ float f2lo(ull v) { return __uint_as_float((unsigned)v); }
__device__ __forceinline__ float f2hi(ull v) { return __uint_as_float((unsigned)(v >> 32)); }
__device__ __forceinline__ ull dupf(float x) {
    ull d; unsigned b = __float_as_uint(x);
    asm("mov.b64 %0, {%1, %2};" : "=l"(d) : "r"(b), "r"(b));
    return d;
}
__device__ __forceinline__ void fma2(ull& acc, ull a, ull b) {
    asm("fma.rn.f32x2 %0, %1, %2, %0;" : "+l"(acc) : "l"(a), "l"(b));
}

// ---------------- prep: transpose weights, reset tags ----------------
__global__ void prep_c(const float* __restrict__ Wih_c, const float* __restrict__ Whh_c) {
    int idx = blockIdx.x * blockDim.x + threadIdx.x;
    if (idx >= KC * GC) return;
    int k = idx / GC, g = idx % GC;
    g_WcT[idx] = (k < CE) ? Wih_c[g * CE + k] : Whh_c[g * CE + (k - CE)];
}

__global__ void prep_w(const float* __restrict__ Wih_w) {
    int idx = blockIdx.x * blockDim.x + threadIdx.x;
    if (idx < 2 * HDIM) g_hpair[idx] = 0xFFFFFFFF00000000ull;   // tag = -1
    if (idx >= KW * GW) return;
    int k = idx / GW, g = idx % GW;
    g_WihwT[idx] = Wih_w[g * KW + k];
}

// ---------------- char LSTM: 16 words/block, k-major smem, f32x2 word pairs ----------------
// SMEM: xh2[512][18] (x|h, layout [k][word]), gates[16][1024]
__global__ void __launch_bounds__(256) char_lstm(
    const int*   __restrict__ char_idxs,
    const int*   __restrict__ char_lens,
    const float* __restrict__ char_emb,
    const float* __restrict__ bih_c,
    const float* __restrict__ bhh_c)
{
    extern __shared__ float sm[];
    float* xh2   = sm;                 // KC * XHS
    float* gates = sm + KC * XHS;      // CWPB * GC
    const int tid   = threadIdx.x;     // 0..255
    const int wbase = blockIdx.x * CWPB;

    float bias[4];
#pragma unroll
    for (int q = 0; q < 4; q++) bias[q] = bih_c[4 * tid + q] + bhh_c[4 * tid + q];

    float c[CWPB];
    int   len[CWPB];
#pragma unroll
    for (int w = 0; w < CWPB; w++) {
        c[w]   = 0.f;
        len[w] = char_lens[wbase + w];
        xh2[(CE + tid) * XHS + w] = 0.f;   // h rows = 0
    }
    __syncthreads();

    const float4* Wp = reinterpret_cast<const float4*>(g_WcT) + tid;  // gate cols 4tid..

    for (int t = 0; t < LMAX; t++) {
        // gather x_t for the 16 words (k-major layout)
#pragma unroll
        for (int w = 0; w < CWPB; w++) {
            int ci = char_idxs[(wbase + w) * LMAX + t];
            xh2[tid * XHS + w] = char_emb[ci * CE + tid];
        }
        __syncthreads();

        ull acc[8][4];   // word-pair wp -> (word 2wp | 2wp+1)
#pragma unroll
        for (int wp = 0; wp < 8; wp++)
#pragma unroll
            for (int q = 0; q < 4; q++) acc[wp][q] = 0ull;

#pragma unroll 4
        for (int k = 0; k < KC; k++) {
            float4 wv = Wp[k * (GC / 4)];
            ull wd0 = dupf(wv.x), wd1 = dupf(wv.y),
                wd2 = dupf(wv.z), wd3 = dupf(wv.w);
            const float* xrow = xh2 + k * XHS;
#pragma unroll
            for (int wp = 0; wp < 8; wp++) {
                ull xp = *reinterpret_cast<const ull*>(xrow + 2 * wp);
                fma2(acc[wp][0], wd0, xp);
                fma2(acc[wp][1], wd1, xp);
                fma2(acc[wp][2], wd2, xp);
                fma2(acc[wp][3], wd3, xp);
            }
        }
#pragma unroll
        for (int wp = 0; wp < 8; wp++) {
            reinterpret_cast<float4*>(gates + (2 * wp) * GC)[tid] =
                make_float4(f2lo(acc[wp][0]) + bias[0], f2lo(acc[wp][1]) + bias[1],
                            f2lo(acc[wp][2]) + bias[2], f2lo(acc[wp][3]) + bias[3]);
            reinterpret_cast<float4*>(gates + (2 * wp + 1) * GC)[tid] =
                make_float4(f2hi(acc[wp][0]) + bias[0], f2hi(acc[wp][1]) + bias[1],
                            f2hi(acc[wp][2]) + bias[2], f2hi(acc[wp][3]) + bias[3]);
        }
        __syncthreads();

        // cell update: thread tid owns hidden unit tid (torch gate order i,f,g,o)
#pragma unroll
        for (int w = 0; w < CWPB; w++) {
            float ig = gates[w * GC +          tid];
            float fg = gates[w * GC +   CE +   tid];
            float gg = gates[w * GC + 2*CE +   tid];
            float og = gates[w * GC + 3*CE +   tid];
            float cn = sigf(fg) * c[w] + sigf(ig) * tanhf(gg);
            float hn = sigf(og) * tanhf(cn);
            c[w] = cn;
            xh2[(CE + tid) * XHS + w] = hn;
            if (t == len[w] - 1) g_lasth[(wbase + w) * CE + tid] = hn;
        }
        __syncthreads();
    }
}

// ---------------- word-LSTM input GEMM: k-major smem, f32x2 word pairs ----------------
__global__ void __launch_bounds__(256) word_gemm(
    const int*   __restrict__ word_idxs,
    const float* __restrict__ word_emb,
    const float* __restrict__ bih_w,
    const float* __restrict__ bhh_w)
{
    extern __shared__ float xw2[];   // [768][18], k-major
    const int tid   = threadIdx.x;           // 0..255
    const int wbase = blockIdx.x * CWPB;
    const int gq    = blockIdx.y * 256 + tid; // float4 column index 0..1023

#pragma unroll
    for (int w = 0; w < CWPB; w++) {
        int wi = word_idxs[wbase + w];
        xw2[ tid        * XHS + w] = word_emb[wi * WE +       tid];
        xw2[(tid + 256) * XHS + w] = word_emb[wi * WE + 256 + tid];
        xw2[(tid + 512) * XHS + w] = g_lasth[(wbase + w) * CE + tid];
    }
    __syncthreads();

    float bias[4];
#pragma unroll
    for (int q = 0; q < 4; q++) bias[q] = bih_w[4 * gq + q] + bhh_w[4 * gq + q];

    ull acc[8][4];
#pragma unroll
    for (int wp = 0; wp < 8; wp++)
#pragma unroll
        for (int q = 0; q < 4; q++) acc[wp][q] = 0ull;

    const float4* Wp = reinterpret_cast<const float4*>(g_WihwT) + gq;
#pragma unroll 4
    for (int k = 0; k < KW; k++) {
        float4 wv = Wp[k * (GW / 4)];
        ull wd0 = dupf(wv.x), wd1 = dupf(wv.y),
            wd2 = dupf(wv.z), wd3 = dupf(wv.w);
        const float* xrow = xw2 + k * XHS;
#pragma unroll
        for (int wp = 0; wp < 8; wp++) {
            ull xp = *reinterpret_cast<const ull*>(xrow + 2 * wp);
            fma2(acc[wp][0], wd0, xp);
            fma2(acc[wp][1], wd1, xp);
            fma2(acc[wp][2], wd2, xp);
            fma2(acc[wp][3], wd3, xp);
        }
    }
#pragma unroll
    for (int wp = 0; wp < 8; wp++) {
        reinterpret_cast<float4*>(g_GXw + (size_t)(wbase + 2 * wp) * GW)[gq] =
            make_float4(f2lo(acc[wp][0]) + bias[0], f2lo(acc[wp][1]) + bias[1],
                        f2lo(acc[wp][2]) + bias[2], f2lo(acc[wp][3]) + bias[3]);
        reinterpret_cast<float4*>(g_GXw + (size_t)(wbase + 2 * wp + 1) * GW)[gq] =
            make_float4(f2hi(acc[wp][0]) + bias[0], f2hi(acc[wp][1]) + bias[1],
                        f2hi(acc[wp][2]) + bias[2], f2hi(acc[wp][3]) + bias[3]);
    }
}

// ---------------- word LSTM recurrence: tagged-data sync (R9) + f32x2 FMA ----------------
// 128 blocks x 256 threads. Warp y of block b owns hidden unit u = 8b + y.
// Thread lane covers k-pairs p = i*32+lane (floats 2p, 2p+1), i<16.
__global__ void __launch_bounds__(256, 1) word_lstm(const float* __restrict__ Whh_w,
                                                    float*       __restrict__ out)
{
    __shared__ __align__(16) float hs[2][HDIM];
    const int tid  = threadIdx.x;
    const int lane = tid & 31;
    const int y    = tid >> 5;
    const int u    = blockIdx.x * 8 + y;

    ull w0[16], w1[16], w2[16], w3[16];
    {
        const ull* W0 = reinterpret_cast<const ull*>(Whh_w + (size_t)(0*HDIM + u) * HDIM);
        const ull* W1 = reinterpret_cast<const ull*>(Whh_w + (size_t)(1*HDIM + u) * HDIM);
        const ull* W2 = reinterpret_cast<const ull*>(Whh_w + (size_t)(2*HDIM + u) * HDIM);
        const ull* W3 = reinterpret_cast<const ull*>(Whh_w + (size_t)(3*HDIM + u) * HDIM);
#pragma unroll
        for (int i = 0; i < 16; i++) {
            w0[i] = W0[i*32 + lane];
            w1[i] = W1[i*32 + lane];
            w2[i] = W2[i*32 + lane];
            w3[i] = W3[i*32 + lane];
        }
    }
    float c = 0.f;

    for (int s = 0; s < S_WORDS; s++) {
        // prefetch gx_s (independent of h)
        const float* gx = g_GXw + (size_t)s * GW;
        float gi0 = gx[u];
        float gf0 = gx[HDIM     + u];
        float gg0 = gx[2*HDIM   + u];
        float go0 = gx[3*HDIM   + u];

        ull a0 = 0ull, a1 = 0ull, a2 = 0ull, a3 = 0ull;
        if (s > 0) {
            const int want = s - 1;
            const int slot = want & 1;
            const ull* base = g_hpair + slot * HDIM + tid;

            ull v0, v1, v2, v3;
            unsigned done = 0;
            int rounds = 0;
            do {
                if (!(done & 1u))
                    asm volatile("ld.relaxed.gpu.global.b64 %0, [%1];" : "=l"(v0) : "l"(base));
                if (!(done & 2u))
                    asm volatile("ld.relaxed.gpu.global.b64 %0, [%1];" : "=l"(v1) : "l"(base + 256));
                if (!(done & 4u))
                    asm volatile("ld.relaxed.gpu.global.b64 %0, [%1];" : "=l"(v2) : "l"(base + 512));
                if (!(done & 8u))
                    asm volatile("ld.relaxed.gpu.global.b64 %0, [%1];" : "=l"(v3) : "l"(base + 768));
                if ((int)(v0 >> 32) == want) done |= 1u;
                if ((int)(v1 >> 32) == want) done |= 2u;
                if ((int)(v2 >> 32) == want) done |= 4u;
                if ((int)(v3 >> 32) == want) done |= 8u;
                if (done == 15u) break;
                if (++rounds > 16) __nanosleep(64);   // safety valve only
            } while (true);

            hs[slot][tid      ] = __uint_as_float((unsigned)v0);
            hs[slot][tid + 256] = __uint_as_float((unsigned)v1);
            hs[slot][tid + 512] = __uint_as_float((unsigned)v2);
            hs[slot][tid + 768] = __uint_as_float((unsigned)v3);
            __syncthreads();

            const ull* hp = reinterpret_cast<const ull*>(hs[slot]);
#pragma unroll
            for (int i = 0; i < 16; i++) {
                ull hv = hp[i * 32 + lane];
                fma2(a0, w0[i], hv);
                fma2(a1, w1[i], hv);
                fma2(a2, w2[i], hv);
                fma2(a3, w3[i], hv);
            }
        }
        float s0 = f2lo(a0) + f2hi(a0);
        float s1 = f2lo(a1) + f2hi(a1);
        float s2 = f2lo(a2) + f2hi(a2);
        float s3 = f2lo(a3) + f2hi(a3);
#pragma unroll
        for (int off = 16; off > 0; off >>= 1) {
            s0 += __shfl_xor_sync(0xffffffffu, s0, off);
            s1 += __shfl_xor_sync(0xffffffffu, s1, off);
            s2 += __shfl_xor_sync(0xffffffffu, s2, off);
            s3 += __shfl_xor_sync(0xffffffffu, s3, off);
        }

        float cn = sigf(gf0 + s1) * c + sigf(gi0 + s0) * tanhf(gg0 + s2);
        c = cn;
        float h = sigf(go0 + s3) * tanhf(cn);

        if (lane == 0) {
            out[(size_t)s * HDIM + u] = h;
            if (s < S_WORDS - 1) {
                ull pv = ((ull)(unsigned)s << 32) | (ull)__float_as_uint(h);
                const ull* ap = g_hpair + (s & 1) * HDIM + u;
                asm volatile("st.relaxed.gpu.global.b64 [%0], %1;" :: "l"(ap), "l"(pv) : "memory");
            }
        }
        // no trailing bar: next step's smem writes go to the other hs slot;
        // the per-step __syncthreads above provides WAR protection.
    }
}

// ---------------- launch ----------------
extern "C" void kernel_launch(void* const* d_in, const int* in_sizes, int n_in,
                              void* d_out, int out_size)
{
    const int*   word_idxs = (const int*)  d_in[0];
    const int*   char_idxs = (const int*)  d_in[1];
    const int*   char_lens = (const int*)  d_in[2];
    const float* char_emb  = (const float*)d_in[3];
    const float* word_emb  = (const float*)d_in[4];
    const float* Wih_c     = (const float*)d_in[5];
    const float* Whh_c     = (const float*)d_in[6];
    const float* bih_c     = (const float*)d_in[7];
    const float* bhh_c     = (const float*)d_in[8];
    const float* Wih_w     = (const float*)d_in[9];
    const float* Whh_w     = (const float*)d_in[10];
    const float* bih_w     = (const float*)d_in[11];
    const float* bhh_w     = (const float*)d_in[12];
    float* out = (float*)d_out;

    const int char_smem = (KC * XHS + CWPB * GC) * (int)sizeof(float);  // 102400 B
    const int gemm_smem = (KW * XHS) * (int)sizeof(float);              // 55296 B
    cudaFuncSetAttribute(char_lstm, cudaFuncAttributeMaxDynamicSharedMemorySize, char_smem);
    cudaFuncSetAttribute(word_gemm, cudaFuncAttributeMaxDynamicSharedMemorySize, gemm_smem);

    prep_c<<<(KC * GC + 255) / 256, 256>>>(Wih_c, Whh_c);
    prep_w<<<(KW * GW + 255) / 256, 256>>>(Wih_w);   // also resets g_hpair tags

    char_lstm<<<S_WORDS / CWPB, 256, char_smem>>>(char_idxs, char_lens, char_emb, bih_c, bhh_c);

    word_gemm<<<dim3(S_WORDS / CWPB, 4), 256, gemm_smem>>>(word_idxs, word_emb, bih_w, bhh_w);

    word_lstm<<<NBLK_WL, 256>>>(Whh_w, out);
}

// round 11
// speedup vs baseline: 1.4556x; 1.4556x over previous
#include <cuda_runtime.h>
#include <cuda_bf16.h>
#include <math.h>

#define S_WORDS 2048
#define LMAX    16
#define CE      256
#define WE      512
#define HDIM    1024
#define GC      (4*CE)     // 1024 gate rows, char LSTM
#define GW      (4*HDIM)   // 4096 gate rows, word LSTM
#define KW      (WE+CE)    // 768  (we | char_feat)
#define ALPHA   256
#define NBLK_WL 128        // persistent blocks for word LSTM (<= 148 SMs)
#define CWPB    16         // words per block, char LSTM

// ---------------- device scratch (no allocations allowed) ----------------
__device__ float g_WcT[2*CE*GC];      // [k=512][g=1024]; rows 0..255 = Wih_c^T, 256.. = Whh_c^T
__device__ float g_CG[ALPHA*GC];      // per-char x-gate table: emb@Wih^T + bias
__device__ float g_WihwT[KW*GW];      // [k=768][g=4096] transposed word input weights
__device__ float g_lasth[S_WORDS*CE]; // char-LSTM output feature per word
__device__ float g_GXw[S_WORDS*GW];   // precomputed x-part of word-LSTM gates (+bias)
// tagged h broadcast: high 32 bits = step tag, low 32 bits = h bits. Double-buffered.
__device__ unsigned long long g_hpair[2*HDIM];

__device__ __forceinline__ float sigf(float x) { return 1.f / (1.f + __expf(-x)); }

// ---------------- prep: transpose weights, reset tags ----------------
__global__ void prep_c(const float* __restrict__ Wih_c, const float* __restrict__ Whh_c) {
    int idx = blockIdx.x * blockDim.x + threadIdx.x;
    if (idx >= 2 * CE * GC) return;
    int k = idx / GC, g = idx % GC;
    g_WcT[idx] = (k < CE) ? Wih_c[g * CE + k] : Whh_c[g * CE + (k - CE)];
}

// CG[ci][g] = sum_k emb[ci][k] * Wih_c[g][k] + bih[g] + bhh[g]; block = one char
__global__ void __launch_bounds__(256) prep_cg(const float* __restrict__ char_emb,
                                               const float* __restrict__ bih_c,
                                               const float* __restrict__ bhh_c) {
    __shared__ float se[CE];
    const int ci  = blockIdx.x;
    const int tid = threadIdx.x;
    se[tid] = char_emb[ci * CE + tid];
    __syncthreads();

    float4 acc = make_float4(bih_c[4*tid+0] + bhh_c[4*tid+0],
                             bih_c[4*tid+1] + bhh_c[4*tid+1],
                             bih_c[4*tid+2] + bhh_c[4*tid+2],
                             bih_c[4*tid+3] + bhh_c[4*tid+3]);
    const float4* Wp = reinterpret_cast<const float4*>(g_WcT) + tid;   // Wih^T half
#pragma unroll 4
    for (int k = 0; k < CE; k++) {
        float4 wv = Wp[k * (GC / 4)];
        float ev = se[k];
        acc.x = fmaf(wv.x, ev, acc.x);
        acc.y = fmaf(wv.y, ev, acc.y);
        acc.z = fmaf(wv.z, ev, acc.z);
        acc.w = fmaf(wv.w, ev, acc.w);
    }
    reinterpret_cast<float4*>(g_CG + ci * GC)[tid] = acc;
}

__global__ void prep_w(const float* __restrict__ Wih_w) {
    int idx = blockIdx.x * blockDim.x + threadIdx.x;
    if (idx < 2 * HDIM) g_hpair[idx] = 0xFFFFFFFF00000000ull;   // tag = -1
    if (idx >= KW * GW) return;
    int k = idx / GW, g = idx % GW;
    g_WihwT[idx] = Wih_w[g * KW + k];
}

// ---------------- char LSTM: 16 words/block; x-gates from CG table, k-loop over h only ----------------
// SMEM: hh[16][256] (h per word), gates[16][1024]   (80 KB)
__global__ void __launch_bounds__(256) char_lstm(
    const int*   __restrict__ char_idxs,
    const int*   __restrict__ char_lens)
{
    extern __shared__ float sm[];
    float* hh    = sm;                // CWPB*256
    float* gates = sm + CWPB * CE;    // CWPB*1024
    const int tid   = threadIdx.x;      // 0..255
    const int wbase = blockIdx.x * CWPB;

    float c[CWPB];
    int   len[CWPB];
#pragma unroll
    for (int w = 0; w < CWPB; w++) {
        c[w]   = 0.f;
        len[w] = char_lens[wbase + w];
        hh[w * CE + tid] = 0.f;   // h = 0
    }
    __syncthreads();

    // Whh^T half of g_WcT, column block 4*tid
    const float4* Wp = reinterpret_cast<const float4*>(g_WcT + CE * GC) + tid;
    const float4* CG4 = reinterpret_cast<const float4*>(g_CG);

    for (int t = 0; t < LMAX; t++) {
        float acc[CWPB][4];
        // init gates from per-char table (coalesced float4 row reads)
#pragma unroll
        for (int w = 0; w < CWPB; w++) {
            int ci = char_idxs[(wbase + w) * LMAX + t];
            float4 cg = CG4[ci * (GC / 4) + tid];
            acc[w][0] = cg.x; acc[w][1] = cg.y; acc[w][2] = cg.z; acc[w][3] = cg.w;
        }

        // h-part: k over 256
#pragma unroll 2
        for (int k = 0; k < CE; k++) {
            float4 wv = Wp[k * (GC / 4)];
#pragma unroll
            for (int w = 0; w < CWPB; w++) {
                float xv = hh[w * CE + k];
                acc[w][0] = fmaf(wv.x, xv, acc[w][0]);
                acc[w][1] = fmaf(wv.y, xv, acc[w][1]);
                acc[w][2] = fmaf(wv.z, xv, acc[w][2]);
                acc[w][3] = fmaf(wv.w, xv, acc[w][3]);
            }
        }
#pragma unroll
        for (int w = 0; w < CWPB; w++) {
            reinterpret_cast<float4*>(gates + w * GC)[tid] =
                make_float4(acc[w][0], acc[w][1], acc[w][2], acc[w][3]);
        }
        __syncthreads();

        // cell update: thread tid owns hidden unit tid (torch gate order i,f,g,o)
#pragma unroll
        for (int w = 0; w < CWPB; w++) {
            float ig = gates[w * GC +          tid];
            float fg = gates[w * GC +   CE +   tid];
            float gg = gates[w * GC + 2*CE +   tid];
            float og = gates[w * GC + 3*CE +   tid];
            float cn = sigf(fg) * c[w] + sigf(ig) * tanhf(gg);
            float hn = sigf(og) * tanhf(cn);
            c[w] = cn;
            hh[w * CE + tid] = hn;
            if (t == len[w] - 1) g_lasth[(wbase + w) * CE + tid] = hn;
        }
        __syncthreads();
    }
}

// ---------------- word-LSTM input GEMM: GXw = [we|last] @ Wih_w^T + bias ----------------
__global__ void word_gemm(const int*   __restrict__ word_idxs,
                          const float* __restrict__ word_emb,
                          const float* __restrict__ bih_w,
                          const float* __restrict__ bhh_w)
{
    extern __shared__ float xw[];   // [8][768]
    const int tid   = threadIdx.x;           // 0..255
    const int wbase = blockIdx.x * 8;
    const int gq    = blockIdx.y * 256 + tid; // float4 column index 0..1023

#pragma unroll
    for (int w = 0; w < 8; w++) {
        int wi = word_idxs[wbase + w];
        xw[w * KW +       tid] = word_emb[wi * WE +       tid];
        xw[w * KW + 256 + tid] = word_emb[wi * WE + 256 + tid];
        xw[w * KW + 512 + tid] = g_lasth[(wbase + w) * CE + tid];
    }
    __syncthreads();

    const int gbase = 4 * gq;
    float bias[4];
#pragma unroll
    for (int q = 0; q < 4; q++) bias[q] = bih_w[gbase + q] + bhh_w[gbase + q];

    float acc[8][4];
#pragma unroll
    for (int w = 0; w < 8; w++)
#pragma unroll
        for (int q = 0; q < 4; q++) acc[w][q] = 0.f;

    const float4* Wp = reinterpret_cast<const float4*>(g_WihwT) + gq;
#pragma unroll 4
    for (int k = 0; k < KW; k++) {
        float4 wv = Wp[k * (GW / 4)];
#pragma unroll
        for (int w = 0; w < 8; w++) {
            float xv = xw[w * KW + k];
            acc[w][0] = fmaf(wv.x, xv, acc[w][0]);
            acc[w][1] = fmaf(wv.y, xv, acc[w][1]);
            acc[w][2] = fmaf(wv.z, xv, acc[w][2]);
            acc[w][3] = fmaf(wv.w, xv, acc[w][3]);
        }
    }
#pragma unroll
    for (int w = 0; w < 8; w++) {
        reinterpret_cast<float4*>(g_GXw + (size_t)(wbase + w) * GW)[gq] =
            make_float4(acc[w][0] + bias[0], acc[w][1] + bias[1],
                        acc[w][2] + bias[2], acc[w][3] + bias[3]);
    }
}

// ---------------- word LSTM recurrence: tagged-data sync, batched polling (R9) ----------------
__global__ void __launch_bounds__(256, 1) word_lstm(const float* __restrict__ Whh_w,
                                                    float*       __restrict__ out)
{
    __shared__ float hs[2][HDIM];
    const int tid  = threadIdx.x;
    const int lane = tid & 31;
    const int y    = tid >> 5;
    const int u    = blockIdx.x * 8 + y;

    float w0[32], w1[32], w2[32], w3[32];
#pragma unroll
    for (int i = 0; i < 32; i++) {
        w0[i] = Whh_w[(size_t)(0 * HDIM + u) * HDIM + i * 32 + lane];
        w1[i] = Whh_w[(size_t)(1 * HDIM + u) * HDIM + i * 32 + lane];
        w2[i] = Whh_w[(size_t)(2 * HDIM + u) * HDIM + i * 32 + lane];
        w3[i] = Whh_w[(size_t)(3 * HDIM + u) * HDIM + i * 32 + lane];
    }
    float c = 0.f;

    for (int s = 0; s < S_WORDS; s++) {
        const float* gx = g_GXw + (size_t)s * GW;
        float gi0 = gx[u];
        float gf0 = gx[HDIM     + u];
        float gg0 = gx[2*HDIM   + u];
        float go0 = gx[3*HDIM   + u];

        float a0 = 0.f, a1 = 0.f, a2 = 0.f, a3 = 0.f;
        if (s > 0) {
            const int want = s - 1;
            const int slot = want & 1;
            const unsigned long long* base = g_hpair + slot * HDIM + tid;

            unsigned long long v0, v1, v2, v3;
            unsigned done = 0;
            int rounds = 0;
            do {
                if (!(done & 1u))
                    asm volatile("ld.relaxed.gpu.global.b64 %0, [%1];" : "=l"(v0) : "l"(base));
                if (!(done & 2u))
                    asm volatile("ld.relaxed.gpu.global.b64 %0, [%1];" : "=l"(v1) : "l"(base + 256));
                if (!(done & 4u))
                    asm volatile("ld.relaxed.gpu.global.b64 %0, [%1];" : "=l"(v2) : "l"(base + 512));
                if (!(done & 8u))
                    asm volatile("ld.relaxed.gpu.global.b64 %0, [%1];" : "=l"(v3) : "l"(base + 768));
                if ((int)(v0 >> 32) == want) done |= 1u;
                if ((int)(v1 >> 32) == want) done |= 2u;
                if ((int)(v2 >> 32) == want) done |= 4u;
                if ((int)(v3 >> 32) == want) done |= 8u;
                if (done == 15u) break;
                if (++rounds > 16) __nanosleep(64);   // safety valve only
            } while (true);

            hs[slot][tid      ] = __uint_as_float((unsigned)v0);
            hs[slot][tid + 256] = __uint_as_float((unsigned)v1);
            hs[slot][tid + 512] = __uint_as_float((unsigned)v2);
            hs[slot][tid + 768] = __uint_as_float((unsigned)v3);
            __syncthreads();

#pragma unroll
            for (int i = 0; i < 32; i++) {
                float hv = hs[slot][i * 32 + lane];
                a0 = fmaf(w0[i], hv, a0);
                a1 = fmaf(w1[i], hv, a1);
                a2 = fmaf(w2[i], hv, a2);
                a3 = fmaf(w3[i], hv, a3);
            }
        }
#pragma unroll
        for (int off = 16; off > 0; off >>= 1) {
            a0 += __shfl_xor_sync(0xffffffffu, a0, off);
            a1 += __shfl_xor_sync(0xffffffffu, a1, off);
            a2 += __shfl_xor_sync(0xffffffffu, a2, off);
            a3 += __shfl_xor_sync(0xffffffffu, a3, off);
        }

        float cn = sigf(gf0 + a1) * c + sigf(gi0 + a0) * tanhf(gg0 + a2);
        c = cn;
        float h = sigf(go0 + a3) * tanhf(cn);

        if (lane == 0) {
            out[(size_t)s * HDIM + u] = h;
            if (s < S_WORDS - 1) {
                unsigned long long pv =
                    ((unsigned long long)(unsigned)s << 32) | (unsigned long long)__float_as_uint(h);
                const unsigned long long* ap = g_hpair + (s & 1) * HDIM + u;
                asm volatile("st.relaxed.gpu.global.b64 [%0], %1;" :: "l"(ap), "l"(pv) : "memory");
            }
        }
    }
}

// ---------------- launch ----------------
extern "C" void kernel_launch(void* const* d_in, const int* in_sizes, int n_in,
                              void* d_out, int out_size)
{
    const int*   word_idxs = (const int*)  d_in[0];
    const int*   char_idxs = (const int*)  d_in[1];
    const int*   char_lens = (const int*)  d_in[2];
    const float* char_emb  = (const float*)d_in[3];
    const float* word_emb  = (const float*)d_in[4];
    const float* Wih_c     = (const float*)d_in[5];
    const float* Whh_c     = (const float*)d_in[6];
    const float* bih_c     = (const float*)d_in[7];
    const float* bhh_c     = (const float*)d_in[8];
    const float* Wih_w     = (const float*)d_in[9];
    const float* Whh_w     = (const float*)d_in[10];
    const float* bih_w     = (const float*)d_in[11];
    const float* bhh_w     = (const float*)d_in[12];
    float* out = (float*)d_out;

    const int char_smem = (CWPB * CE + CWPB * GC) * (int)sizeof(float);  // 81920 B
    const int gemm_smem = 8 * KW * (int)sizeof(float);                   // 24576 B
    cudaFuncSetAttribute(char_lstm, cudaFuncAttributeMaxDynamicSharedMemorySize, char_smem);
    cudaFuncSetAttribute(word_gemm, cudaFuncAttributeMaxDynamicSharedMemorySize, gemm_smem);

    prep_c<<<(2 * CE * GC + 255) / 256, 256>>>(Wih_c, Whh_c);
    prep_cg<<<ALPHA, 256>>>(char_emb, bih_c, bhh_c);        // needs g_WcT (same stream)
    prep_w<<<(KW * GW + 255) / 256, 256>>>(Wih_w);          // also resets g_hpair tags

    char_lstm<<<S_WORDS / CWPB, 256, char_smem>>>(char_idxs, char_lens);

    word_gemm<<<dim3(S_WORDS / 8, 4), 256, gemm_smem>>>(word_idxs, word_emb, bih_w, bhh_w);

    word_lstm<<<NBLK_WL, 256>>>(Whh_w, out);
}

// round 12
// speedup vs baseline: 1.5064x; 1.0349x over previous
#include <cuda_runtime.h>
#include <cuda_bf16.h>
#include <math.h>

#define S_WORDS 2048
#define LMAX    16
#define CE      256
#define WE      512
#define HDIM    1024
#define GC      (4*CE)     // 1024 gate rows, char LSTM
#define GW      (4*HDIM)   // 4096 gate rows, word LSTM
#define KW      (WE+CE)    // 768  (we | char_feat)
#define ALPHA   256
#define NBLK_WL 128        // persistent blocks for word LSTM (<= 148 SMs)
#define CWPB    16         // words per block, char LSTM
#define GWPB    16         // words per block, word gemm

// ---------------- device scratch (no allocations allowed) ----------------
__device__ float g_WcT[2*CE*GC];      // [k=512][g=1024]; rows 0..255 = Wih_c^T, 256.. = Whh_c^T
__device__ float g_CG[ALPHA*GC];      // per-char x-gate table: emb@Wih^T + bias
__device__ float g_WihwT[KW*GW];      // [k=768][g=4096] transposed word input weights
__device__ float g_lasth[S_WORDS*CE]; // char-LSTM output feature per word
__device__ float g_GXw[S_WORDS*GW];   // precomputed x-part of word-LSTM gates (+bias)
// tagged h broadcast: high 32 bits = step tag, low 32 bits = h bits. Double-buffered.
__device__ unsigned long long g_hpair[2*HDIM];

__device__ __forceinline__ float sigf(float x) { return 1.f / (1.f + __expf(-x)); }

// ---------------- prep: transpose weights, reset tags ----------------
__global__ void prep_c(const float* __restrict__ Wih_c, const float* __restrict__ Whh_c) {
    int idx = blockIdx.x * blockDim.x + threadIdx.x;
    if (idx >= 2 * CE * GC) return;
    int k = idx / GC, g = idx % GC;
    g_WcT[idx] = (k < CE) ? Wih_c[g * CE + k] : Whh_c[g * CE + (k - CE)];
}

// CG[ci][g] = sum_k emb[ci][k] * Wih_c[g][k] + bih[g] + bhh[g]; block = one char
__global__ void __launch_bounds__(256) prep_cg(const float* __restrict__ char_emb,
                                               const float* __restrict__ bih_c,
                                               const float* __restrict__ bhh_c) {
    __shared__ float se[CE];
    const int ci  = blockIdx.x;
    const int tid = threadIdx.x;
    se[tid] = char_emb[ci * CE + tid];
    __syncthreads();

    float4 acc = make_float4(bih_c[4*tid+0] + bhh_c[4*tid+0],
                             bih_c[4*tid+1] + bhh_c[4*tid+1],
                             bih_c[4*tid+2] + bhh_c[4*tid+2],
                             bih_c[4*tid+3] + bhh_c[4*tid+3]);
    const float4* Wp = reinterpret_cast<const float4*>(g_WcT) + tid;   // Wih^T half
#pragma unroll 4
    for (int k = 0; k < CE; k++) {
        float4 wv = Wp[k * (GC / 4)];
        float ev = se[k];
        acc.x = fmaf(wv.x, ev, acc.x);
        acc.y = fmaf(wv.y, ev, acc.y);
        acc.z = fmaf(wv.z, ev, acc.z);
        acc.w = fmaf(wv.w, ev, acc.w);
    }
    reinterpret_cast<float4*>(g_CG + ci * GC)[tid] = acc;
}

__global__ void prep_w(const float* __restrict__ Wih_w) {
    int idx = blockIdx.x * blockDim.x + threadIdx.x;
    if (idx < 2 * HDIM) g_hpair[idx] = 0xFFFFFFFF00000000ull;   // tag = -1
    if (idx >= KW * GW) return;
    int k = idx / GW, g = idx % GW;
    g_WihwT[idx] = Wih_w[g * KW + k];
}

// ---------------- char LSTM: 16 words/block, 512 threads (float2 gate cols) ----------------
// SMEM: hh[16][256] (h per word), gates[16][1024]   (80 KB)
__global__ void __launch_bounds__(512) char_lstm(
    const int*   __restrict__ char_idxs,
    const int*   __restrict__ char_lens)
{
    extern __shared__ float sm[];
    float* hh    = sm;                // CWPB*256
    float* gates = sm + CWPB * CE;    // CWPB*1024
    const int tid   = threadIdx.x;      // 0..511
    const int wbase = blockIdx.x * CWPB;
    const int unit  = tid & 255;        // hidden unit owned for cell update
    const int wgrp  = (tid >> 8) * 8;   // word group 0..7 or 8..15

    float c[8];
    int   len[8];
#pragma unroll
    for (int j = 0; j < 8; j++) {
        int w = wgrp + j;
        c[j]   = 0.f;
        len[j] = char_lens[wbase + w];
        hh[w * CE + unit] = 0.f;   // each (w,unit) written by exactly one thread
    }
    __syncthreads();

    // Whh^T half of g_WcT; thread owns float2 gate columns {2tid, 2tid+1}
    const float2* Wp  = reinterpret_cast<const float2*>(g_WcT + (size_t)CE * GC) + tid;
    const float2* CG2 = reinterpret_cast<const float2*>(g_CG);

    for (int t = 0; t < LMAX; t++) {
        float acc[CWPB][2];
        // init gates from per-char table (coalesced float2 row reads)
#pragma unroll
        for (int w = 0; w < CWPB; w++) {
            int ci = char_idxs[(wbase + w) * LMAX + t];
            float2 cg = CG2[ci * (GC / 2) + tid];
            acc[w][0] = cg.x; acc[w][1] = cg.y;
        }

        // h-part: k over 256 (hh reads are warp-broadcast)
#pragma unroll 4
        for (int k = 0; k < CE; k++) {
            float2 wv = Wp[k * (GC / 2)];
#pragma unroll
            for (int w = 0; w < CWPB; w++) {
                float xv = hh[w * CE + k];
                acc[w][0] = fmaf(wv.x, xv, acc[w][0]);
                acc[w][1] = fmaf(wv.y, xv, acc[w][1]);
            }
        }
#pragma unroll
        for (int w = 0; w < CWPB; w++)
            reinterpret_cast<float2*>(gates + w * GC)[tid] = make_float2(acc[w][0], acc[w][1]);
        __syncthreads();

        // cell update: thread handles its 8 words for unit `unit` (torch order i,f,g,o)
#pragma unroll
        for (int j = 0; j < 8; j++) {
            int w = wgrp + j;
            float ig = gates[w * GC +          unit];
            float fg = gates[w * GC +   CE +   unit];
            float gg = gates[w * GC + 2*CE +   unit];
            float og = gates[w * GC + 3*CE +   unit];
            float cn = sigf(fg) * c[j] + sigf(ig) * tanhf(gg);
            float hn = sigf(og) * tanhf(cn);
            c[j] = cn;
            hh[w * CE + unit] = hn;
            if (t == len[j] - 1) g_lasth[(wbase + w) * CE + unit] = hn;
        }
        __syncthreads();
    }
}

// ---------------- word-LSTM input GEMM: 16 words/block (halved weight re-streaming) ----------------
__global__ void __launch_bounds__(256) word_gemm(
    const int*   __restrict__ word_idxs,
    const float* __restrict__ word_emb,
    const float* __restrict__ bih_w,
    const float* __restrict__ bhh_w)
{
    extern __shared__ float xw[];   // [16][768]
    const int tid   = threadIdx.x;           // 0..255
    const int wbase = blockIdx.x * GWPB;
    const int gq    = blockIdx.y * 256 + tid; // float4 column index 0..1023

#pragma unroll
    for (int w = 0; w < GWPB; w++) {
        int wi = word_idxs[wbase + w];
        xw[w * KW +       tid] = word_emb[wi * WE +       tid];
        xw[w * KW + 256 + tid] = word_emb[wi * WE + 256 + tid];
        xw[w * KW + 512 + tid] = g_lasth[(wbase + w) * CE + tid];
    }
    __syncthreads();

    const int gbase = 4 * gq;
    float bias[4];
#pragma unroll
    for (int q = 0; q < 4; q++) bias[q] = bih_w[gbase + q] + bhh_w[gbase + q];

    float acc[GWPB][4];
#pragma unroll
    for (int w = 0; w < GWPB; w++)
#pragma unroll
        for (int q = 0; q < 4; q++) acc[w][q] = 0.f;

    const float4* Wp = reinterpret_cast<const float4*>(g_WihwT) + gq;
#pragma unroll 2
    for (int k = 0; k < KW; k++) {
        float4 wv = Wp[k * (GW / 4)];
#pragma unroll
        for (int w = 0; w < GWPB; w++) {
            float xv = xw[w * KW + k];
            acc[w][0] = fmaf(wv.x, xv, acc[w][0]);
            acc[w][1] = fmaf(wv.y, xv, acc[w][1]);
            acc[w][2] = fmaf(wv.z, xv, acc[w][2]);
            acc[w][3] = fmaf(wv.w, xv, acc[w][3]);
        }
    }
#pragma unroll
    for (int w = 0; w < GWPB; w++) {
        reinterpret_cast<float4*>(g_GXw + (size_t)(wbase + w) * GW)[gq] =
            make_float4(acc[w][0] + bias[0], acc[w][1] + bias[1],
                        acc[w][2] + bias[2], acc[w][3] + bias[3]);
    }
}

// ---------------- word LSTM recurrence: tagged-data sync, batched polling (R9) ----------------
__global__ void __launch_bounds__(256, 1) word_lstm(const float* __restrict__ Whh_w,
                                                    float*       __restrict__ out)
{
    __shared__ float hs[2][HDIM];
    const int tid  = threadIdx.x;
    const int lane = tid & 31;
    const int y    = tid >> 5;
    const int u    = blockIdx.x * 8 + y;

    float w0[32], w1[32], w2[32], w3[32];
#pragma unroll
    for (int i = 0; i < 32; i++) {
        w0[i] = Whh_w[(size_t)(0 * HDIM + u) * HDIM + i * 32 + lane];
        w1[i] = Whh_w[(size_t)(1 * HDIM + u) * HDIM + i * 32 + lane];
        w2[i] = Whh_w[(size_t)(2 * HDIM + u) * HDIM + i * 32 + lane];
        w3[i] = Whh_w[(size_t)(3 * HDIM + u) * HDIM + i * 32 + lane];
    }
    float c = 0.f;

    for (int s = 0; s < S_WORDS; s++) {
        const float* gx = g_GXw + (size_t)s * GW;
        float gi0 = gx[u];
        float gf0 = gx[HDIM     + u];
        float gg0 = gx[2*HDIM   + u];
        float go0 = gx[3*HDIM   + u];

        float a0 = 0.f, a1 = 0.f, a2 = 0.f, a3 = 0.f;
        if (s > 0) {
            const int want = s - 1;
            const int slot = want & 1;
            const unsigned long long* base = g_hpair + slot * HDIM + tid;

            unsigned long long v0, v1, v2, v3;
            unsigned done = 0;
            int rounds = 0;
            do {
                if (!(done & 1u))
                    asm volatile("ld.relaxed.gpu.global.b64 %0, [%1];" : "=l"(v0) : "l"(base));
                if (!(done & 2u))
                    asm volatile("ld.relaxed.gpu.global.b64 %0, [%1];" : "=l"(v1) : "l"(base + 256));
                if (!(done & 4u))
                    asm volatile("ld.relaxed.gpu.global.b64 %0, [%1];" : "=l"(v2) : "l"(base + 512));
                if (!(done & 8u))
                    asm volatile("ld.relaxed.gpu.global.b64 %0, [%1];" : "=l"(v3) : "l"(base + 768));
                if ((int)(v0 >> 32) == want) done |= 1u;
                if ((int)(v1 >> 32) == want) done |= 2u;
                if ((int)(v2 >> 32) == want) done |= 4u;
                if ((int)(v3 >> 32) == want) done |= 8u;
                if (done == 15u) break;
                if (++rounds > 16) __nanosleep(64);   // safety valve only
            } while (true);

            hs[slot][tid      ] = __uint_as_float((unsigned)v0);
            hs[slot][tid + 256] = __uint_as_float((unsigned)v1);
            hs[slot][tid + 512] = __uint_as_float((unsigned)v2);
            hs[slot][tid + 768] = __uint_as_float((unsigned)v3);
            __syncthreads();

#pragma unroll
            for (int i = 0; i < 32; i++) {
                float hv = hs[slot][i * 32 + lane];
                a0 = fmaf(w0[i], hv, a0);
                a1 = fmaf(w1[i], hv, a1);
                a2 = fmaf(w2[i], hv, a2);
                a3 = fmaf(w3[i], hv, a3);
            }
        }
#pragma unroll
        for (int off = 16; off > 0; off >>= 1) {
            a0 += __shfl_xor_sync(0xffffffffu, a0, off);
            a1 += __shfl_xor_sync(0xffffffffu, a1, off);
            a2 += __shfl_xor_sync(0xffffffffu, a2, off);
            a3 += __shfl_xor_sync(0xffffffffu, a3, off);
        }

        float cn = sigf(gf0 + a1) * c + sigf(gi0 + a0) * tanhf(gg0 + a2);
        c = cn;
        float h = sigf(go0 + a3) * tanhf(cn);

        if (lane == 0) {
            out[(size_t)s * HDIM + u] = h;
            if (s < S_WORDS - 1) {
                unsigned long long pv =
                    ((unsigned long long)(unsigned)s << 32) | (unsigned long long)__float_as_uint(h);
                const unsigned long long* ap = g_hpair + (s & 1) * HDIM + u;
                asm volatile("st.relaxed.gpu.global.b64 [%0], %1;" :: "l"(ap), "l"(pv) : "memory");
            }
        }
    }
}

// ---------------- launch ----------------
extern "C" void kernel_launch(void* const* d_in, const int* in_sizes, int n_in,
                              void* d_out, int out_size)
{
    const int*   word_idxs = (const int*)  d_in[0];
    const int*   char_idxs = (const int*)  d_in[1];
    const int*   char_lens = (const int*)  d_in[2];
    const float* char_emb  = (const float*)d_in[3];
    const float* word_emb  = (const float*)d_in[4];
    const float* Wih_c     = (const float*)d_in[5];
    const float* Whh_c     = (const float*)d_in[6];
    const float* bih_c     = (const float*)d_in[7];
    const float* bhh_c     = (const float*)d_in[8];
    const float* Wih_w     = (const float*)d_in[9];
    const float* Whh_w     = (const float*)d_in[10];
    const float* bih_w     = (const float*)d_in[11];
    const float* bhh_w     = (const float*)d_in[12];
    float* out = (float*)d_out;

    const int char_smem = (CWPB * CE + CWPB * GC) * (int)sizeof(float);  // 81920 B
    const int gemm_smem = GWPB * KW * (int)sizeof(float);                // 49152 B
    cudaFuncSetAttribute(char_lstm, cudaFuncAttributeMaxDynamicSharedMemorySize, char_smem);
    cudaFuncSetAttribute(word_gemm, cudaFuncAttributeMaxDynamicSharedMemorySize, gemm_smem);

    prep_c<<<(2 * CE * GC + 255) / 256, 256>>>(Wih_c, Whh_c);
    prep_cg<<<ALPHA, 256>>>(char_emb, bih_c, bhh_c);        // needs g_WcT (same stream)
    prep_w<<<(KW * GW + 255) / 256, 256>>>(Wih_w);          // also resets g_hpair tags

    char_lstm<<<S_WORDS / CWPB, 512, char_smem>>>(char_idxs, char_lens);

    word_gemm<<<dim3(S_WORDS / GWPB, 4), 256, gemm_smem>>>(word_idxs, word_emb, bih_w, bhh_w);

    word_lstm<<<NBLK_WL, 256>>>(Whh_w, out);
}